// round 2
// baseline (speedup 1.0000x reference)
#include <cuda_runtime.h>
#include <math.h>

#define Bc 2
#define Sc 2048
#define Dc 1024
#define Hc 16
#define DKc 64
#define BSc (Bc*Sc)   // 4096

// Scratch (no allocations allowed)
__device__ float g_qkv[(size_t)BSc * 3 * Dc];      // [B,S,3,H,DK]
__device__ float g_q[(size_t)Bc*Hc*Sc*DKc];        // [B,H,S,DK]
__device__ float g_k[(size_t)Bc*Hc*Sc*DKc];
__device__ float g_v[(size_t)Bc*Hc*Sc*DKc];
__device__ float g_attn[(size_t)BSc * Dc];         // [B,S,D]

// ---------------------------------------------------------------------------
// Classic 128x128x8 SGEMM, 256 threads, 8x8 per thread. Dims must be
// multiples of 128 (M) / 128 (N) / 8 (K) — true for all uses here.
// ---------------------------------------------------------------------------
__global__ void sgemm_kernel(const float* __restrict__ A,
                             const float* __restrict__ Bm,
                             float* __restrict__ C,
                             int M, int N, int K) {
    __shared__ float As[8 * 132];   // [k][m] with pad 4 -> conflict-free stores
    __shared__ float Bs[8 * 128];   // [k][n]

    const int tid = threadIdx.x;
    const int tx = tid & 15;
    const int ty = tid >> 4;
    const int m0 = blockIdx.y << 7;
    const int n0 = blockIdx.x << 7;

    float acc[8][8];
#pragma unroll
    for (int i = 0; i < 8; i++)
#pragma unroll
        for (int j = 0; j < 8; j++) acc[i][j] = 0.f;

    for (int k0 = 0; k0 < K; k0 += 8) {
#pragma unroll
        for (int i = 0; i < 4; i++) {
            int e = tid + (i << 8);
            int m = e >> 3, kk = e & 7;
            As[kk * 132 + m] = A[(size_t)(m0 + m) * K + k0 + kk];
        }
#pragma unroll
        for (int i = 0; i < 4; i++) {
            int e = tid + (i << 8);
            int kk = e >> 7, n = e & 127;
            Bs[kk * 128 + n] = Bm[(size_t)(k0 + kk) * N + n0 + n];
        }
        __syncthreads();

#pragma unroll
        for (int kk = 0; kk < 8; kk++) {
            float a[8], bb[8];
#pragma unroll
            for (int i = 0; i < 8; i++) a[i] = As[kk * 132 + ty * 8 + i];
#pragma unroll
            for (int j = 0; j < 8; j++) bb[j] = Bs[kk * 128 + tx * 8 + j];
#pragma unroll
            for (int i = 0; i < 8; i++)
#pragma unroll
                for (int j = 0; j < 8; j++) acc[i][j] += a[i] * bb[j];
        }
        __syncthreads();
    }

#pragma unroll
    for (int i = 0; i < 8; i++)
#pragma unroll
        for (int j = 0; j < 8; j++)
            C[(size_t)(m0 + ty * 8 + i) * N + n0 + tx * 8 + j] = acc[i][j];
}

// ---------------------------------------------------------------------------
// RoPE + split heads. qkv: [B,S,3,H,DK]. Writes Q/K/V as [B,H,S,DK].
// Replicates the reference table math in fp32 to minimize divergence.
// ---------------------------------------------------------------------------
__global__ void rope_split_kernel(const float* __restrict__ qkv,
                                  float* __restrict__ Q,
                                  float* __restrict__ Kp,
                                  float* __restrict__ V) {
    int idx = blockIdx.x * blockDim.x + threadIdx.x;  // [b][s][h][d]
    int d = idx & 63;
    int h = (idx >> 6) & (Hc - 1);
    int s = (idx >> 10) & (Sc - 1);
    int b = idx >> 21;

    const float* base = qkv + (size_t)(b * Sc + s) * 3 * Dc + h * DKc;
    float qv = base[d];
    float kv = base[Dc + d];
    float vv = base[2 * Dc + d];

    int d2 = d & 31;
    float invf = 1.0f / powf(10000.0f, (float)d2 * (1.0f / 32.0f));
    float ang = (float)s * invf;
    float sn, c;
    sincosf(ang, &sn, &c);

    int dp = d ^ 32;            // rotate_half partner
    float qp = base[dp];
    float kp = base[Dc + dp];
    float sgn = (d < 32) ? -1.0f : 1.0f;

    float qo = qv * c + sgn * qp * sn;
    float ko = kv * c + sgn * kp * sn;

    size_t o = ((size_t)(b * Hc + h) * Sc + s) * DKc + d;
    Q[o] = qo;
    Kp[o] = ko;
    V[o] = vv;
}

// ---------------------------------------------------------------------------
// Flash attention: 64x64 tiles, online softmax, causal skipping.
// 256 threads; thread (ty,tx) owns a 4x4 micro-tile.
// SMEM: Qs transposed [d][r] pad65, KP union (K^T tile / P tile), Vs [j][dv].
// ---------------------------------------------------------------------------
__global__ void flash_attn_kernel(const float* __restrict__ Q,
                                  const float* __restrict__ K,
                                  const float* __restrict__ V,
                                  float* __restrict__ Out) {
    extern __shared__ float sm[];
    float* Qs  = sm;                 // [64][65] : Qs[d*65 + r]
    float* KP  = sm + 64 * 65;       // Ks_t[d*65 + c]  OR  Ps[r*65 + c]
    float* Vs  = KP + 64 * 65;       // [64][64] : Vs[j*64 + dv]
    float* mS  = Vs + 64 * 64;       // [64]
    float* lS  = mS + 64;            // [64]
    float* corr = lS + 64;           // [64]

    const int tid = threadIdx.x;
    const int tx = tid & 15;
    const int ty = tid >> 4;
    const int bh = blockIdx.x;       // b*H + h
    const int qt = blockIdx.y;
    const int q0 = qt * 64;

    const float* Qb = Q + (size_t)bh * Sc * DKc;
    const float* Kb = K + (size_t)bh * Sc * DKc;
    const float* Vb = V + (size_t)bh * Sc * DKc;

    // Load Q tile (pre-scaled by 1/sqrt(dk))
#pragma unroll
    for (int i = 0; i < 16; i++) {
        int e = tid + i * 256;
        int r = e >> 6, d = e & 63;
        Qs[d * 65 + r] = Qb[(size_t)(q0 + r) * DKc + d] * 0.125f;
    }
    if (tid < 64) { mS[tid] = -INFINITY; lS[tid] = 0.f; }
    __syncthreads();

    float acc[4][4];
#pragma unroll
    for (int i = 0; i < 4; i++)
#pragma unroll
        for (int j = 0; j < 4; j++) acc[i][j] = 0.f;

    const int nkt = qt + 1;          // causal: only key tiles <= query tile
    for (int kt = 0; kt < nkt; kt++) {
        const int k0 = kt * 64;

        // Load K^T tile and V tile
#pragma unroll
        for (int i = 0; i < 16; i++) {
            int e = tid + i * 256;
            int c = e >> 6, d = e & 63;
            KP[d * 65 + c] = Kb[(size_t)(k0 + c) * DKc + d];
        }
#pragma unroll
        for (int i = 0; i < 16; i++) {
            int e = tid + i * 256;
            int j = e >> 6, dv = e & 63;
            Vs[j * 64 + dv] = Vb[(size_t)(k0 + j) * DKc + dv];
        }
        __syncthreads();

        // Scores: S = (Q*scale) @ K^T
        float sreg[4][4];
#pragma unroll
        for (int i = 0; i < 4; i++)
#pragma unroll
            for (int j = 0; j < 4; j++) sreg[i][j] = 0.f;

#pragma unroll
        for (int d = 0; d < 64; d++) {
            float a[4], bb[4];
#pragma unroll
            for (int i = 0; i < 4; i++) a[i] = Qs[d * 65 + ty * 4 + i];
#pragma unroll
            for (int j = 0; j < 4; j++) bb[j] = KP[d * 65 + tx * 4 + j];
#pragma unroll
            for (int i = 0; i < 4; i++)
#pragma unroll
                for (int j = 0; j < 4; j++) sreg[i][j] += a[i] * bb[j];
        }
        __syncthreads();   // all K^T reads done before overwriting KP with P

        // Causal mask (only possible on the diagonal tile) + write raw scores
        const bool diag = (kt == qt);
#pragma unroll
        for (int i = 0; i < 4; i++)
#pragma unroll
            for (int j = 0; j < 4; j++) {
                float sv = sreg[i][j];
                if (diag && (tx * 4 + j > ty * 4 + i)) sv = -INFINITY;
                KP[(ty * 4 + i) * 65 + tx * 4 + j] = sv;
            }
        __syncthreads();

        // Online softmax row statistics (threads 0..63, one per row)
        if (tid < 64) {
            const int r = tid;
            float mold = mS[r];
            float mx = mold;
            for (int c = 0; c < 64; c++) mx = fmaxf(mx, KP[r * 65 + c]);
            float cr = expf(mold - mx);       // 0 on first tile (mold=-inf)
            float sum = 0.f;
            for (int c = 0; c < 64; c++) {
                float p = expf(KP[r * 65 + c] - mx);
                KP[r * 65 + c] = p;
                sum += p;
            }
            lS[r] = lS[r] * cr + sum;
            mS[r] = mx;
            corr[r] = cr;
        }
        __syncthreads();

        // Rescale accumulators and do P @ V
        float cr[4];
#pragma unroll
        for (int i = 0; i < 4; i++) cr[i] = corr[ty * 4 + i];
#pragma unroll
        for (int i = 0; i < 4; i++)
#pragma unroll
            for (int j = 0; j < 4; j++) acc[i][j] *= cr[i];

#pragma unroll 16
        for (int j = 0; j < 64; j++) {
            float a[4], bb[4];
#pragma unroll
            for (int i = 0; i < 4; i++) a[i] = KP[(ty * 4 + i) * 65 + j];
#pragma unroll
            for (int x = 0; x < 4; x++) bb[x] = Vs[j * 64 + tx * 4 + x];
#pragma unroll
            for (int i = 0; i < 4; i++)
#pragma unroll
                for (int x = 0; x < 4; x++) acc[i][x] += a[i] * bb[x];
        }
        __syncthreads();   // protect KP/Vs before next tile's loads
    }

    // Normalize and write out as [B,S,H*DK]
    const int b = bh >> 4;
    const int h = bh & 15;
    float inv[4];
#pragma unroll
    for (int i = 0; i < 4; i++) inv[i] = 1.0f / lS[ty * 4 + i];
#pragma unroll
    for (int i = 0; i < 4; i++)
#pragma unroll
        for (int j = 0; j < 4; j++)
            Out[(size_t)(b * Sc + q0 + ty * 4 + i) * Dc + h * DKc + tx * 4 + j] =
                acc[i][j] * inv[i];
}

// ---------------------------------------------------------------------------
extern "C" void kernel_launch(void* const* d_in, const int* in_sizes, int n_in,
                              void* d_out, int out_size) {
    const float* x    = (const float*)d_in[0];   // [B,S,D]
    const float* Wqkv = (const float*)d_in[1];   // [D, 3D]
    const float* Wo   = (const float*)d_in[2];   // [D, D]
    float* out = (float*)d_out;

    float *qkv, *q, *k, *v, *attn;
    cudaGetSymbolAddress((void**)&qkv,  g_qkv);
    cudaGetSymbolAddress((void**)&q,    g_q);
    cudaGetSymbolAddress((void**)&k,    g_k);
    cudaGetSymbolAddress((void**)&v,    g_v);
    cudaGetSymbolAddress((void**)&attn, g_attn);

    // 1. QKV projection: [4096,1024] @ [1024,3072]
    sgemm_kernel<<<dim3(3 * Dc / 128, BSc / 128), 256>>>(x, Wqkv, qkv, BSc, 3 * Dc, Dc);

    // 2. RoPE + head split
    rope_split_kernel<<<(Bc * Sc * Hc * DKc) / 256, 256>>>(qkv, q, k, v);

    // 3. Causal flash attention
    const int smem = (64 * 65 * 2 + 64 * 64 + 3 * 64) * (int)sizeof(float);  // 50432 B
    cudaFuncSetAttribute(flash_attn_kernel,
                         cudaFuncAttributeMaxDynamicSharedMemorySize, smem);
    flash_attn_kernel<<<dim3(Bc * Hc, Sc / 64), 256, smem>>>(q, k, v, attn);

    // 4. Output projection: [4096,1024] @ [1024,1024]
    sgemm_kernel<<<dim3(Dc / 128, BSc / 128), 256>>>(attn, Wo, out, BSc, Dc, Dc);
}